// round 17
// baseline (speedup 1.0000x reference)
#include <cuda_runtime.h>
#include <cuda_bf16.h>
#include <cstdint>

#define N_NODES 100000
#define N_EDGES 600000
#define D_IN    128
#define D_OUT   96
#define N_REL   4

#define TILE_M    32
#define N_TILES32 3125               // 100000/32 exact

#define ROW_BYTES 272                // 128 bf16 (256B) + 16B pad -> conflict-free ldmatrix
#define A_SPLIT   (TILE_M * ROW_BYTES)     // 8704 (one split, one buffer)
#define A_BUF     (2 * A_SPLIT)            // 17408 (hi+lo, one buffer)
#define A_TOTAL   (2 * A_BUF)              // 34816 (double buffered)
#define B1_SPLIT  (128 * ROW_BYTES)        // 34816
#define B2_SPLIT  (96 * ROW_BYTES)         // 26112

// ---------------- scratch (static device globals; no allocs allowed) --------
// NOTE: zero-initialized at module load; tail_zero re-zeroes after every run.
__device__ __align__(16) float g_out1[(size_t)N_NODES * D_IN];          // 51.2 MB
__device__ int      g_cnt[N_NODES * N_REL];
__device__ int      g_cursor[N_NODES * N_REL];
__device__ int      g_base[N_NODES];
__device__ int      g_total;
__device__ uint32_t g_csr[N_EDGES];

// weight images (bf16 hi/lo, padded rows). B2 rows 96 only.
__device__ uint4 g_B1hi[5 * (B1_SPLIT / 16)];
__device__ uint4 g_B1lo[5 * (B1_SPLIT / 16)];
__device__ uint4 g_B2hi[5 * (B2_SPLIT / 16)];
__device__ uint4 g_B2lo[5 * (B2_SPLIT / 16)];

// ---------------- helpers ----------------------------------------------------
__device__ __forceinline__ uint32_t smem_u32(const void* p) {
    uint32_t a;
    asm("{ .reg .u64 t; cvta.to.shared.u64 t, %1; cvt.u32.u64 %0, t; }" : "=r"(a) : "l"(p));
    return a;
}

#define LDSM4(r, addr)                                                        \
    asm volatile("ldmatrix.sync.aligned.m8n8.x4.shared.b16 {%0,%1,%2,%3}, [%4];" \
                 : "=r"((r)[0]), "=r"((r)[1]), "=r"((r)[2]), "=r"((r)[3])     \
                 : "r"(addr))

#define MMA16816(d, a, b0, b1)                                                \
    asm volatile("mma.sync.aligned.m16n8k16.row.col.f32.bf16.bf16.f32 "       \
                 "{%0,%1,%2,%3},{%4,%5,%6,%7},{%8,%9},{%0,%1,%2,%3};"         \
                 : "+f"((d)[0]), "+f"((d)[1]), "+f"((d)[2]), "+f"((d)[3])     \
                 : "r"((a)[0]), "r"((a)[1]), "r"((a)[2]), "r"((a)[3]),        \
                   "r"(b0), "r"(b1))

#define CP_ASYNC16(saddr, gptr)                                               \
    asm volatile("cp.async.cg.shared.global [%0], [%1], 16;"                  \
                 :: "r"(saddr), "l"(gptr))
#define CP_COMMIT()  asm volatile("cp.async.commit_group;" ::: "memory")
#define CP_WAIT0()   asm volatile("cp.async.wait_group 0;" ::: "memory")

#define BAR_SYNC(id, cnt)   asm volatile("bar.sync %0, %1;"   :: "r"(id), "r"(cnt) : "memory")
#define BAR_ARRIVE(id, cnt) asm volatile("bar.arrive %0, %1;" :: "r"(id), "r"(cnt) : "memory")
// barrier ids: 1,2 = A(buf) READY; 3,4 = A(buf) FREE; 5 = B ready (consumers); 6 = B free (consumers)

__device__ __forceinline__ uint32_t pack_bf16x2(__nv_bfloat16 a, __nv_bfloat16 b) {
    uint32_t r;
    asm("mov.b32 %0, {%1, %2};" : "=r"(r)
        : "h"(*(unsigned short*)&a), "h"(*(unsigned short*)&b));
    return r;
}

__device__ __forceinline__ void split_store8(char* hi_p, char* lo_p, float4 v) {
    __nv_bfloat16 h0 = __float2bfloat16(v.x), h1 = __float2bfloat16(v.y);
    __nv_bfloat16 h2 = __float2bfloat16(v.z), h3 = __float2bfloat16(v.w);
    __nv_bfloat16 l0 = __float2bfloat16(v.x - __bfloat162float(h0));
    __nv_bfloat16 l1 = __float2bfloat16(v.y - __bfloat162float(h1));
    __nv_bfloat16 l2 = __float2bfloat16(v.z - __bfloat162float(h2));
    __nv_bfloat16 l3 = __float2bfloat16(v.w - __bfloat162float(h3));
    *(uint2*)hi_p = make_uint2(pack_bf16x2(h0, h1), pack_bf16x2(h2, h3));
    *(uint2*)lo_p = make_uint2(pack_bf16x2(l0, l1), pack_bf16x2(l2, l3));
}

__device__ __forceinline__ float4 relu4(float4 v) {
    v.x = fmaxf(v.x, 0.f); v.y = fmaxf(v.y, 0.f);
    v.z = fmaxf(v.z, 0.f); v.w = fmaxf(v.w, 0.f);
    return v;
}

// ---------------- launch 1: edge count + weight image build ------------------
__global__ void count_prep(const int* __restrict__ ei, const int* __restrict__ et,
                           const float* __restrict__ W1, const float* __restrict__ root1,
                           const float* __restrict__ W2, const float* __restrict__ root2)
{
    int idx = blockIdx.x * blockDim.x + threadIdx.x;
    if (idx < N_EDGES) atomicAdd(&g_cnt[ei[N_EDGES + idx] * N_REL + et[idx]], 1);
    if (idx < 5 * 128 * 128) {
        int batch = idx / 16384, r = idx % 16384;
        int k = r / 128, n = r % 128;
        float v = (batch < 4) ? W1[(size_t)batch * 16384 + k * 128 + n] : root1[k * 128 + n];
        __nv_bfloat16 hi = __float2bfloat16(v);
        __nv_bfloat16 lo = __float2bfloat16(v - __bfloat162float(hi));
        size_t off = (size_t)batch * B1_SPLIT + (size_t)n * ROW_BYTES + (size_t)k * 2;
        *(__nv_bfloat16*)((char*)g_B1hi + off) = hi;
        *(__nv_bfloat16*)((char*)g_B1lo + off) = lo;
    }
    if (idx < 5 * 128 * 96) {
        int batch = idx / 12288, r = idx % 12288;
        int k = r / 96, n = r % 96;
        float v = (batch < 4) ? W2[(size_t)batch * 12288 + k * 96 + n] : root2[k * 96 + n];
        __nv_bfloat16 hi = __float2bfloat16(v);
        __nv_bfloat16 lo = __float2bfloat16(v - __bfloat162float(hi));
        size_t off = (size_t)batch * B2_SPLIT + (size_t)n * ROW_BYTES + (size_t)k * 2;
        *(__nv_bfloat16*)((char*)g_B2hi + off) = hi;
        *(__nv_bfloat16*)((char*)g_B2lo + off) = lo;
    }
}

// ---------------- launch 2: per-dst base allocation (order-free) -------------
__global__ void alloc_base_kernel() {
    int d = blockIdx.x * blockDim.x + threadIdx.x;
    if (d < N_NODES) {
        int deg = g_cnt[d*4] + g_cnt[d*4+1] + g_cnt[d*4+2] + g_cnt[d*4+3];
        g_base[d] = atomicAdd(&g_total, deg);
    }
}

// ---------------- launch 3: CSR reorder --------------------------------------
__global__ void reorder_kernel(const int* __restrict__ ei, const int* __restrict__ et) {
    int e = blockIdx.x * blockDim.x + threadIdx.x;
    if (e >= N_EDGES) return;
    int src = ei[e];
    int dst = ei[N_EDGES + e];
    int t   = et[e];
    int pos = atomicAdd(&g_cursor[dst * N_REL + t], 1);
    int sub = 0;
#pragma unroll
    for (int j = 0; j < N_REL - 1; j++) if (j < t) sub += g_cnt[dst * N_REL + j];
    g_csr[g_base[dst] + sub + pos] = (uint32_t)src;
}

// ---------------- launch 6: tail zero (restores invariant for next run) ------
__global__ void tail_zero() {
    int i = blockIdx.x * blockDim.x + threadIdx.x;
    if (i == 0) g_total = 0;
    if (i < N_NODES * N_REL) { g_cnt[i] = 0; g_cursor[i] = 0; }
}

// ---------------- launches 4+5: warp-specialized fused aggregate+GEMM --------
// TILE_M=32, 512 threads, 2 CTAs/SM. Warps 8-15 = producers: gather+split A(b)
// into double-buffered A smem (4 rows each). Warps 0-7 = consumers: cp.async B,
// MMA 16x32 warp tiles, persistent fp32 acc across the 5 batches, epilogue.
template <int DOUT, int SRC>   // SRC 0: feats = x (ext); 1: feats = relu(g_out1)
__global__ __launch_bounds__(512, 2)
void gemm_ws(const float* __restrict__ xext, const float* __restrict__ bias,
             float* __restrict__ out_ext)
{
    constexpr int B_SPLIT = (DOUT == 128) ? B1_SPLIT : B2_SPLIT;
    constexpr int B_U4    = B_SPLIT / 16;
    extern __shared__ char smem[];

    int tid = threadIdx.x;
    int wid = tid >> 5, lane = tid & 31;
    int tile = blockIdx.x;
    uint32_t sb = smem_u32(smem);

    const float* feats = (SRC == 0) ? xext : g_out1;
    float* Obuf = (DOUT == 128) ? g_out1 : out_ext;

    if (wid >= 8) {
        // ================= PRODUCER (warps 8-15): stage A ====================
        int pw = wid - 8;
        int my_row = pw * 4 + (lane & 3);
        int my_d   = tile * TILE_M + my_row;
        int4 cw = make_int4(0, 0, 0, 0);
        int  bs = 0;
        if (my_d < N_NODES) {
            cw = *(const int4*)&g_cnt[my_d * 4];
            bs = g_base[my_d];
        }
        int ps1 = cw.x, ps2 = cw.x + cw.y, ps3 = ps2 + cw.z;
        int deg_total = ps3 + cw.w;

        uint32_t eidx[4];
#pragma unroll
        for (int i = 0; i < 4; i++) {
            int base = __shfl_sync(0xFFFFFFFFu, bs, i);
            int deg  = __shfl_sync(0xFFFFFFFFu, deg_total, i);
            eidx[i] = (lane < deg) ? g_csr[base + lane] : 0u;
        }

#pragma unroll 1
        for (int b = 0; b < 5; b++) {
            if (b >= 2) BAR_SYNC(3 + (b & 1), 512);   // wait A-buf free
            char* sAhi = smem + (b & 1) * A_BUF;
            char* sAlo = sAhi + A_SPLIT;

            int c_sel   = (b == 0) ? cw.x : (b == 1) ? cw.y
                        : (b == 2) ? cw.z : cw.w;
            int sub_sel = (b == 0) ? 0 : (b == 1) ? ps1
                        : (b == 2) ? ps2 : ps3;

#pragma unroll 1
            for (int i = 0; i < 4; i++) {
                int dl = pw * 4 + i;
                int d  = tile * TILE_M + dl;
                float4 a = make_float4(0.f, 0.f, 0.f, 0.f);
                if (d < N_NODES) {
                    if (b < 4) {
                        int c   = __shfl_sync(0xFFFFFFFFu, c_sel,   i);
                        int sub = __shfl_sync(0xFFFFFFFFu, sub_sel, i);
                        float4 a1 = make_float4(0.f, 0.f, 0.f, 0.f);
                        if (sub + c <= 32) {
                            int e = 0;
                            for (; e + 1 < c; e += 2) {
                                int s0 = __shfl_sync(0xFFFFFFFFu, eidx[i], sub + e);
                                int s1 = __shfl_sync(0xFFFFFFFFu, eidx[i], sub + e + 1);
                                float4 v0 = ((const float4*)(feats + (size_t)s0 * 128))[lane];
                                float4 v1 = ((const float4*)(feats + (size_t)s1 * 128))[lane];
                                if (SRC == 1) { v0 = relu4(v0); v1 = relu4(v1); }
                                a.x += v0.x;  a.y += v0.y;  a.z += v0.z;  a.w += v0.w;
                                a1.x += v1.x; a1.y += v1.y; a1.z += v1.z; a1.w += v1.w;
                            }
                            if (e < c) {
                                int s0 = __shfl_sync(0xFFFFFFFFu, eidx[i], sub + e);
                                float4 v0 = ((const float4*)(feats + (size_t)s0 * 128))[lane];
                                if (SRC == 1) v0 = relu4(v0);
                                a.x += v0.x; a.y += v0.y; a.z += v0.z; a.w += v0.w;
                            }
                        } else {
                            int base = __shfl_sync(0xFFFFFFFFu, bs, i);
                            const uint32_t* ep = g_csr + base + sub;
                            for (int e = 0; e < c; e++) {
                                int s0 = ep[e];
                                float4 v0 = ((const float4*)(feats + (size_t)s0 * 128))[lane];
                                if (SRC == 1) v0 = relu4(v0);
                                a.x += v0.x; a.y += v0.y; a.z += v0.z; a.w += v0.w;
                            }
                        }
                        float nm = 1.f / (float)(c > 1 ? c : 1);
                        a.x = (a.x + a1.x) * nm; a.y = (a.y + a1.y) * nm;
                        a.z = (a.z + a1.z) * nm; a.w = (a.w + a1.w) * nm;
                    } else {
                        a = ((const float4*)(feats + (size_t)d * 128))[lane];
                        if (SRC == 1) a = relu4(a);
                    }
                }
                split_store8(sAhi + (size_t)dl * ROW_BYTES + lane * 8,
                             sAlo + (size_t)dl * ROW_BYTES + lane * 8, a);
            }
            BAR_ARRIVE(1 + (b & 1), 512);             // A(b) ready
        }
        return;   // producers exit; no remaining barrier involves them
    }

    // ================= CONSUMER (warps 0-7): B load + MMA ====================
    int warp_m = (wid & 1) * 16;
    int warp_n = (wid >> 1) * 32;
    bool active = (warp_n < DOUT);

    uint32_t aoff = (uint32_t)(warp_m + (lane & 15)) * ROW_BYTES + ((lane >> 4) & 1) * 16;
    uint32_t boff = (uint32_t)(warp_n + (lane & 7) + ((lane >> 4) & 1) * 8) * ROW_BYTES
                  + ((lane >> 3) & 1) * 16;

    float acc[4][4];
#pragma unroll
    for (int j = 0; j < 4; j++)
#pragma unroll
        for (int q = 0; q < 4; q++) acc[j][q] = 0.f;

    // issue B(0)
    {
        const uint4* bhi = (DOUT == 128 ? g_B1hi : g_B2hi);
        const uint4* blo = (DOUT == 128 ? g_B1lo : g_B2lo);
        for (int i = tid; i < B_U4; i += 256) {
            CP_ASYNC16(sb + A_TOTAL + i * 16, bhi + i);
            CP_ASYNC16(sb + A_TOTAL + B_SPLIT + i * 16, blo + i);
        }
        CP_COMMIT();
    }

#pragma unroll 1
    for (int b = 0; b < 5; b++) {
        CP_WAIT0();
        BAR_SYNC(5, 256);                 // all consumers' B(b) chunks visible
        BAR_SYNC(1 + (b & 1), 512);       // A(b) staged by producers

        if (active) {
            uint32_t aA[2], bA[2][2];
#pragma unroll
            for (int s = 0; s < 2; s++) {
                aA[s] = sb + (b & 1) * A_BUF + s * A_SPLIT + aoff;
#pragma unroll
                for (int jj = 0; jj < 2; jj++)
                    bA[s][jj] = sb + A_TOTAL + s * B_SPLIT + boff + jj * 16 * ROW_BYTES;
            }
#pragma unroll
            for (int kk = 0; kk < 8; kk++) {
                uint32_t ah[4], al[4], bh[2][4], bl[2][4];
                LDSM4(ah, aA[0]);
                LDSM4(al, aA[1]);
                aA[0] += 32; aA[1] += 32;
#pragma unroll
                for (int jj = 0; jj < 2; jj++) {
                    LDSM4(bh[jj], bA[0][jj]);
                    LDSM4(bl[jj], bA[1][jj]);
                    bA[0][jj] += 32; bA[1][jj] += 32;
                }
#pragma unroll
                for (int j = 0; j < 4; j++) {
                    int jj = j >> 1, q = (j & 1) * 2;
                    MMA16816(acc[j], ah, bh[jj][q], bh[jj][q + 1]);
                    MMA16816(acc[j], ah, bl[jj][q], bl[jj][q + 1]);
                    MMA16816(acc[j], al, bh[jj][q], bh[jj][q + 1]);
                }
            }
        }

        if (b <= 2) BAR_ARRIVE(3 + (b & 1), 512);   // A-buf free for reuse
        if (b < 4) {
            BAR_SYNC(6, 256);             // all consumers done reading B(b)
            const uint4* bhi = (DOUT == 128 ? g_B1hi : g_B2hi) + (size_t)(b + 1) * B_U4;
            const uint4* blo = (DOUT == 128 ? g_B1lo : g_B2lo) + (size_t)(b + 1) * B_U4;
            for (int i = tid; i < B_U4; i += 256) {
                CP_ASYNC16(sb + A_TOTAL + i * 16, bhi + i);
                CP_ASYNC16(sb + A_TOTAL + B_SPLIT + i * 16, blo + i);
            }
            CP_COMMIT();
        }
    }

    // ---- epilogue: complete layer output = agg + root + bias ---------------
    if (active) {
        int row0 = tile * TILE_M + warp_m + (lane >> 2);
#pragma unroll
        for (int j = 0; j < 4; j++) {
            int col = warp_n + j * 8 + (lane & 3) * 2;
            if (col >= DOUT) continue;
            float b0 = bias[col], b1 = bias[col + 1];
            float2 v0 = make_float2(acc[j][0] + b0, acc[j][1] + b1);
            float2 v1 = make_float2(acc[j][2] + b0, acc[j][3] + b1);
            if (row0 < N_NODES)
                *(float2*)(Obuf + (size_t)row0 * DOUT + col) = v0;
            if (row0 + 8 < N_NODES)
                *(float2*)(Obuf + (size_t)(row0 + 8) * DOUT + col) = v1;
        }
    }
}

// ---------------- launch -----------------------------------------------------
#define SMEM1 (A_TOTAL + 2 * B1_SPLIT)   // 34816 + 69632 = 104448 -> 2 CTAs/SM
#define SMEM2 (A_TOTAL + 2 * B2_SPLIT)   // 34816 + 52224 =  87040 -> 2 CTAs/SM

extern "C" void kernel_launch(void* const* d_in, const int* in_sizes, int n_in,
                              void* d_out, int out_size)
{
    const float* x     = (const float*)d_in[0];
    const int*   ei    = (const int*)d_in[1];
    const int*   et    = (const int*)d_in[2];
    const float* W1    = (const float*)d_in[3];
    const float* root1 = (const float*)d_in[4];
    const float* b1    = (const float*)d_in[5];
    const float* W2    = (const float*)d_in[6];
    const float* root2 = (const float*)d_in[7];
    const float* b2    = (const float*)d_in[8];
    float* out = (float*)d_out;

    cudaFuncSetAttribute(gemm_ws<128,0>, cudaFuncAttributeMaxDynamicSharedMemorySize, SMEM1);
    cudaFuncSetAttribute(gemm_ws<96,1>,  cudaFuncAttributeMaxDynamicSharedMemorySize, SMEM2);

    // counters are zero on entry (module-load init first call; tail_zero after).
    count_prep<<<(N_EDGES + 255) / 256, 256>>>(ei, et, W1, root1, W2, root2);  // #1
    alloc_base_kernel<<<(N_NODES + 255) / 256, 256>>>();                       // #2
    reorder_kernel<<<(N_EDGES + 255) / 256, 256>>>(ei, et);                    // #3
    gemm_ws<128,0><<<N_TILES32, 512, SMEM1>>>(x, b1, nullptr);                 // #4 (profiled)
    gemm_ws<96,1><<<N_TILES32, 512, SMEM2>>>(nullptr, b2, out);                // #5
    tail_zero<<<(N_NODES * N_REL + 255) / 256, 256>>>();                       // #6
}